// round 16
// baseline (speedup 1.0000x reference)
#include <cuda_runtime.h>
#include <cuda_fp16.h>
#include <math.h>
#include <stdint.h>

#define L   256
#define DM  128
#define NH  4
#define DK  32
#define NP  (L*L)
#define WS  136   // big-tile stride (halves)
#define AS  40    // small-tile stride (halves)

__device__ __align__(16) __half g_att[NP*DM];
__device__ __align__(16) __half g_zn[NP*DM];     // LN output, half
__device__ __align__(16) __half g_biasH[NH*NP];  // [h][i*L+j], *log2e, mask-folded
__device__ __align__(16) __half g_wT[5*128*WS];  // half W images [k][n], padded

__device__ __forceinline__ uint32_t smem_u32(const void* p){
    uint32_t a;
    asm("{ .reg .u64 t; cvta.to.shared.u64 t, %1; cvt.u32.u64 %0, t; }" : "=r"(a) : "l"(p));
    return a;
}
__device__ __forceinline__ void mma16(float* c, const uint32_t* a, const uint32_t* b){
    asm volatile("mma.sync.aligned.m16n8k16.row.col.f32.f16.f16.f32 "
        "{%0,%1,%2,%3}, {%4,%5,%6,%7}, {%8,%9}, {%0,%1,%2,%3};\n"
        : "+f"(c[0]), "+f"(c[1]), "+f"(c[2]), "+f"(c[3])
        : "r"(a[0]), "r"(a[1]), "r"(a[2]), "r"(a[3]), "r"(b[0]), "r"(b[1]));
}
__device__ __forceinline__ void ldsm4(uint32_t* r, uint32_t a){
    asm volatile("ldmatrix.sync.aligned.m8n8.x4.shared.b16 {%0,%1,%2,%3}, [%4];"
        : "=r"(r[0]), "=r"(r[1]), "=r"(r[2]), "=r"(r[3]) : "r"(a));
}
__device__ __forceinline__ void ldsm4t(uint32_t* r, uint32_t a){
    asm volatile("ldmatrix.sync.aligned.m8n8.x4.trans.shared.b16 {%0,%1,%2,%3}, [%4];"
        : "=r"(r[0]), "=r"(r[1]), "=r"(r[2]), "=r"(r[3]) : "r"(a));
}
__device__ __forceinline__ void ldsm2t(uint32_t* r, uint32_t a){
    asm volatile("ldmatrix.sync.aligned.m8n8.x2.trans.shared.b16 {%0,%1}, [%2];"
        : "=r"(r[0]), "=r"(r[1]) : "r"(a));
}
__device__ __forceinline__ uint32_t h2u(__half2 h){ return *(uint32_t*)&h; }
__device__ __forceinline__ float ex2(float x){
    float r; asm("ex2.approx.f32 %0, %1;" : "=f"(r) : "f"(x)); return r;
}

// ---------------------------------------------------------------------------
// K1: blocks 0..4: weight images; blocks 5+: LN + bias (4 positions per warp)
// ---------------------------------------------------------------------------
__global__ __launch_bounds__(512) void k_ln(const float* __restrict__ z,
    const float* __restrict__ ln_w, const float* __restrict__ ln_b,
    const float* __restrict__ Wb, const float* __restrict__ mask,
    const float* __restrict__ Wq, const float* __restrict__ Wk,
    const float* __restrict__ Wv, const float* __restrict__ Wg,
    const float* __restrict__ Wo)
{
    if (blockIdx.x < 5){
        int m = blockIdx.x;
        const float* W = (m==0)?Wq:(m==1)?Wk:(m==2)?Wv:(m==3)?Wg:Wo;
        __half* dst = g_wT + m*128*WS;
        for (int e = threadIdx.x; e < 128*32; e += 512){
            int k = e>>5, c4 = e&31;
            float4 v = *(const float4*)&W[k*128 + c4*4];
            uint2 u = { h2u(__floats2half2_rn(v.x, v.y)), h2u(__floats2half2_rn(v.z, v.w)) };
            *(uint2*)&dst[k*WS + c4*4] = u;
        }
        return;
    }
    const float LOG2E = 1.4426950408889634f;
    int w = threadIdx.x>>5, lane = threadIdx.x&31;
    int pbase = (blockIdx.x-5)*64 + w*4;
    float4 lw = *(const float4*)&ln_w[lane*4];
    float4 lb = *(const float4*)&ln_b[lane*4];
    float4 w0 = *(const float4*)&Wb[(4*lane+0)*NH];
    float4 w1 = *(const float4*)&Wb[(4*lane+1)*NH];
    float4 w2 = *(const float4*)&Wb[(4*lane+2)*NH];
    float4 w3 = *(const float4*)&Wb[(4*lane+3)*NH];
    #pragma unroll
    for (int pp=0; pp<4; pp++){
        int p = pbase + pp;
        float4 x = *(const float4*)&z[(size_t)p*DM + lane*4];
        float s = x.x+x.y+x.z+x.w;
        float sq = x.x*x.x+x.y*x.y+x.z*x.z+x.w*x.w;
        #pragma unroll
        for (int o=16;o>0;o>>=1){
            s  += __shfl_xor_sync(0xffffffffu, s,  o);
            sq += __shfl_xor_sync(0xffffffffu, sq, o);
        }
        float mu = s*(1.0f/DM);
        float var = fmaxf(sq*(1.0f/DM) - mu*mu, 0.0f);
        float rstd = rsqrtf(var + 1e-5f);
        float zn0=(x.x-mu)*rstd*lw.x+lb.x, zn1=(x.y-mu)*rstd*lw.y+lb.y;
        float zn2=(x.z-mu)*rstd*lw.z+lb.z, zn3=(x.w-mu)*rstd*lw.w+lb.w;
        uint2 u = { h2u(__floats2half2_rn(zn0,zn1)), h2u(__floats2half2_rn(zn2,zn3)) };
        *(uint2*)&g_zn[(size_t)p*DM + lane*4] = u;
        float a0 = zn0*w0.x+zn1*w1.x+zn2*w2.x+zn3*w3.x;
        float a1 = zn0*w0.y+zn1*w1.y+zn2*w2.y+zn3*w3.y;
        float a2 = zn0*w0.z+zn1*w1.z+zn2*w2.z+zn3*w3.z;
        float a3 = zn0*w0.w+zn1*w1.w+zn2*w2.w+zn3*w3.w;
        #pragma unroll
        for (int o=16;o>0;o>>=1){
            a0 += __shfl_xor_sync(0xffffffffu, a0, o);
            a1 += __shfl_xor_sync(0xffffffffu, a1, o);
            a2 += __shfl_xor_sync(0xffffffffu, a2, o);
            a3 += __shfl_xor_sync(0xffffffffu, a3, o);
        }
        if (lane==0){
            float mf = mask[p>>8]*mask[p&255];
            float ninf = -__int_as_float(0x7f800000);
            g_biasH[0*NP+p] = __float2half(mf>0.f ? a0*LOG2E : ninf);
            g_biasH[1*NP+p] = __float2half(mf>0.f ? a1*LOG2E : ninf);
            g_biasH[2*NP+p] = __float2half(mf>0.f ? a2*LOG2E : ninf);
            g_biasH[3*NP+p] = __float2half(mf>0.f ? a3*LOG2E : ninf);
        }
    }
}

// PV tile for jt given ph fragments (macro so it inlines at both sites)
#define PV_TILE(JB) do { \
    _Pragma("unroll") \
    for (int kc2=0;kc2<4;kc2++){ \
        uint32_t pa[4] = { ph[2*kc2][0], ph[2*kc2][1], ph[2*kc2+1][0], ph[2*kc2+1][1] }; \
        _Pragma("unroll") \
        for (int pr=0;pr<2;pr++){ \
            uint32_t b[4]; \
            ldsm4t(b, sV + (((JB) + kc2*16 + (lane&7) + (((lane>>3)&1)<<3))*AS \
                             + pr*16 + ((lane>>4)<<3))*2); \
            mma16(oacc[2*pr],   pa, &b[0]); \
            mma16(oacc[2*pr+1], pa, &b[2]); \
        } \
        uint32_t bS[2]; \
        ldsm2t(bS, sV + (((JB) + kc2*16 + (lane&7) + (((lane>>3)&1)<<3))*AS + 32)*2); \
        mma16(oaccS, pa, bS); \
    } \
} while(0)

#define QK_TILE(JB) do { \
    _Pragma("unroll") \
    for (int nt=0;nt<8;nt++) \
        _Pragma("unroll") \
        for (int u=0;u<4;u++) sacc[nt][u]=0.f; \
    _Pragma("unroll") \
    for (int kc=0;kc<2;kc++){ \
        _Pragma("unroll") \
        for (int pr=0;pr<4;pr++){ \
            uint32_t b[4]; \
            ldsm4(b, sK + (((JB) + pr*16 + (lane&7) + ((lane>>4)<<3))*AS \
                            + kc*16 + (((lane>>3)&1)<<3))*2); \
            mma16(sacc[2*pr],   qa[kc], &b[0]); \
            mma16(sacc[2*pr+1], qa[kc], &b[2]); \
        } \
    } \
} while(0)

#define EXP_TILE(JB) do { \
    _Pragma("unroll") \
    for (int nt=0;nt<8;nt++){ \
        int j0 = (JB) + nt*8 + 2*t4; \
        _Pragma("unroll") \
        for (int rp=0;rp<2;rp++){ \
            int i = rb + g + 8*rp; \
            float2 bi = __half22float2(*(const __half2*)&g_biasH[h*NP + i*L + j0]); \
            float p0 = ex2(sacc[nt][2*rp]   + bi.x); \
            float p1 = ex2(sacc[nt][2*rp+1] + bi.y); \
            ph[nt][rp] = h2u(__floats2half2_rn(p0, p1)); \
        } \
    } \
} while(0)

// ---------------------------------------------------------------------------
// K2: fused per (row r, head h): proj -> attention -> g_att. grid (L, NH).
// Attention jt loop software-pipelined: QK(jt) | PV(jt-1) | exp(jt).
// ---------------------------------------------------------------------------
__global__ __launch_bounds__(512,1) void k_main(const float* __restrict__ bg)
{
    extern __shared__ char smem[];
    __half* As = (__half*)smem;
    __half* Qt = (__half*)(smem + 69632);
    __half* Kt = Qt + 256*AS;
    __half* Vt = Kt + 256*AS;
    __half* Gt = Vt + 256*AS;
    __half* Wsl = Gt + 256*AS;
    uint32_t sAs = smem_u32(As), sQ = smem_u32(Qt), sK = smem_u32(Kt),
             sV = smem_u32(Vt), sWsl = smem_u32(Wsl);
    int r = blockIdx.x, h = blockIdx.y;
    int tid = threadIdx.x, w = tid>>5, lane = tid&31, g = lane>>2, t4 = lane&3;
    const float SC = 0.17677669529663687f * 1.4426950408889634f;

    for (int e = tid; e < 4096; e += 512){
        int row = e>>4, c = e&15;
        ((uint4*)&As[row*WS])[c] = ((const uint4*)&g_zn[(size_t)(r*L+row)*DM])[c];
    }
    for (int e = tid; e < 2048; e += 512){
        int m = e>>9, k = (e>>2)&127, c = e&3;
        *((uint4*)&Wsl[m*128*AS + k*AS + c*8]) =
            *((const uint4*)&g_wT[m*128*WS + k*WS + h*32 + c*8]);
    }
    if (tid < 256){
        uint4 ones = { 0x00003C00u, 0u, 0u, 0u };
        *(uint4*)&Vt[tid*AS + 32] = ones;
    }
    __syncthreads();
    {
        int wm = w>>1, wn = w&1, rb = wm*32;
        uint32_t afrag[8][2][4];
        #pragma unroll
        for (int kc=0; kc<8; kc++)
            #pragma unroll
            for (int mt=0; mt<2; mt++)
                ldsm4(afrag[kc][mt],
                      sAs + ((rb + mt*16 + (lane&15))*WS + kc*16 + ((lane>>4)<<3))*2);
        #pragma unroll 1
        for (int mode=0; mode<4; mode++){
            uint32_t sWm = sWsl + mode*(128*AS*2);
            __half* Tt = (mode==0)?Qt:(mode==1)?Kt:(mode==2)?Vt:Gt;
            float acc[2][2][4];
            #pragma unroll
            for (int mt=0;mt<2;mt++)
                #pragma unroll
                for (int nt=0;nt<2;nt++)
                    #pragma unroll
                    for (int u=0;u<4;u++) acc[mt][nt][u]=0.f;
            #pragma unroll
            for (int kc=0; kc<8; kc++){
                int k0 = kc*16;
                uint32_t b[4];
                ldsm4t(b, sWm + ((k0 + (lane&7) + (((lane>>3)&1)<<3))*AS
                                  + wn*16 + ((lane>>4)<<3))*2);
                #pragma unroll
                for (int mt=0;mt<2;mt++){
                    mma16(acc[mt][0], afrag[kc][mt], &b[0]);
                    mma16(acc[mt][1], afrag[kc][mt], &b[2]);
                }
            }
            #pragma unroll
            for (int mt=0;mt<2;mt++)
                #pragma unroll
                for (int nt=0;nt<2;nt++){
                    int col = wn*16 + nt*8 + 2*t4;
                    #pragma unroll
                    for (int rp=0;rp<2;rp++){
                        int row = rb + mt*16 + g + 8*rp;
                        float v0 = acc[mt][nt][2*rp], v1 = acc[mt][nt][2*rp+1];
                        if (mode==0){ v0 *= SC; v1 *= SC; }
                        else if (mode==3){
                            v0 = 1.f/(1.f + __expf(-(v0 + bg[h*32+col])));
                            v1 = 1.f/(1.f + __expf(-(v1 + bg[h*32+col+1])));
                        }
                        *(__half2*)&Tt[row*AS + col] = __floats2half2_rn(v0, v1);
                    }
                }
        }
    }
    __syncthreads();
    {
        int rb = w*16;
        uint32_t qa[2][4];
        #pragma unroll
        for (int kc=0;kc<2;kc++)
            ldsm4(qa[kc], sQ + ((rb + (lane&15))*AS + kc*16 + ((lane>>4)<<3))*2);
        float oacc[4][4];
        float oaccS[4];
        #pragma unroll
        for (int nt=0;nt<4;nt++)
            #pragma unroll
            for (int u=0;u<4;u++) oacc[nt][u]=0.f;
        #pragma unroll
        for (int u=0;u<4;u++) oaccS[u]=0.f;

        float sacc[8][4];
        uint32_t ph[8][2];
        // prologue: QK(0) + exp(0)
        QK_TILE(0);
        EXP_TILE(0);
        // pipelined: QK(jt) | PV(jt-1) | exp(jt)
        #pragma unroll
        for (int jt=1; jt<4; jt++){
            int jb = jt*64;
            QK_TILE(jb);
            PV_TILE(jb - 64);
            EXP_TILE(jb);
        }
        // epilogue: PV(3)
        PV_TILE(192);

        float s0 = __shfl_sync(0xffffffffu, oaccS[0], lane & ~3);
        float s1 = __shfl_sync(0xffffffffu, oaccS[2], lane & ~3);
        float rinv[2] = { 1.f/s0, 1.f/s1 };
        #pragma unroll
        for (int nt=0;nt<4;nt++)
            #pragma unroll
            for (int rp=0;rp<2;rp++){
                int i = rb + g + 8*rp;
                int d = nt*8 + 2*t4;
                float2 gf = __half22float2(*(__half2*)&Gt[i*AS + d]);
                *(__half2*)&g_att[(size_t)(r*L+i)*DM + h*DK + d] = __floats2half2_rn(
                    oacc[nt][2*rp]  *rinv[rp]*gf.x,
                    oacc[nt][2*rp+1]*rinv[rp]*gf.y);
            }
    }
}

// ---------------------------------------------------------------------------
// K3: out = g_att @ Wo + bo. PERSISTENT: 296 CTAs x 256 thr, 2 CTAs/SM.
// ---------------------------------------------------------------------------
__global__ __launch_bounds__(256,2) void k_out(const float* __restrict__ bo,
                                               float* __restrict__ dout)
{
    extern __shared__ char smem[];
    __half* At0 = (__half*)smem;
    __half* At1 = (__half*)(smem + 64*WS*2);
    __half* Ws  = (__half*)(smem + 2*64*WS*2);
    uint32_t sAtB[2] = { smem_u32(At0), smem_u32(At1) };
    uint32_t sW = smem_u32(Ws);
    int tid = threadIdx.x, w = tid>>5, lane = tid&31, g = lane>>2, t4 = lane&3;
    int wm = w>>2, wn = w&3;

    for (int e = tid; e < 128*WS/8; e += 256)
        ((uint4*)Ws)[e] = ((const uint4*)(g_wT + 4*128*WS))[e];
    {
        int p0 = blockIdx.x*64;
        for (int e = tid; e < 1024; e += 256){
            int row = e>>4, c = e&15;
            ((uint4*)At0)[row*17 + c] = ((const uint4*)g_att)[(size_t)(p0+row)*16 + c];
        }
    }
    __syncthreads();

    float boL[4][2];
    #pragma unroll
    for (int nt=0;nt<4;nt++){
        boL[nt][0] = bo[wn*32 + nt*8 + 2*t4];
        boL[nt][1] = bo[wn*32 + nt*8 + 2*t4 + 1];
    }

    int buf = 0;
    for (int pb = blockIdx.x; pb < 1024; pb += gridDim.x){
        int nxt = pb + gridDim.x;
        if (nxt < 1024){
            __half* Atn = buf ? At0 : At1;
            int p0n = nxt*64;
            for (int e = tid; e < 1024; e += 256){
                int row = e>>4, c = e&15;
                ((uint4*)Atn)[row*17 + c] = ((const uint4*)g_att)[(size_t)(p0n+row)*16 + c];
            }
        }
        uint32_t sAt = sAtB[buf];
        int p0 = pb*64;
        int rb = wm*32;
        float acc[2][4][4];
        #pragma unroll
        for (int mt=0;mt<2;mt++)
            #pragma unroll
            for (int nt=0;nt<4;nt++)
                #pragma unroll
                for (int u=0;u<4;u++) acc[mt][nt][u]=0.f;
        #pragma unroll
        for (int kc=0; kc<8; kc++){
            int k0 = kc*16;
            uint32_t a[2][4];
            #pragma unroll
            for (int mt=0;mt<2;mt++)
                ldsm4(a[mt], sAt + ((rb + mt*16 + (lane&15))*WS + k0 + ((lane>>4)<<3))*2);
            uint32_t b[4][4];
            #pragma unroll
            for (int pr=0;pr<2;pr++)
                ldsm4t(b[2*pr], sW + ((k0 + (lane&7) + (((lane>>3)&1)<<3))*WS
                                       + wn*32 + pr*16 + ((lane>>4)<<3))*2);
            #pragma unroll
            for (int mt=0;mt<2;mt++)
                #pragma unroll
                for (int nt=0;nt<4;nt++)
                    mma16(acc[mt][nt], a[mt], &b[nt&~1][(nt&1)*2]);
        }
        #pragma unroll
        for (int mt=0;mt<2;mt++)
            #pragma unroll
            for (int nt=0;nt<4;nt++){
                int col = wn*32 + nt*8 + 2*t4;
                #pragma unroll
                for (int rp=0;rp<2;rp++){
                    int row = p0 + rb + mt*16 + g + 8*rp;
                    float2 o2 = { acc[mt][nt][2*rp] + boL[nt][0],
                                  acc[mt][nt][2*rp+1] + boL[nt][1] };
                    *(float2*)&dout[(size_t)row*DM + col] = o2;
                }
            }
        buf ^= 1;
        __syncthreads();
    }
}

// ---------------------------------------------------------------------------
extern "C" void kernel_launch(void* const* d_in, const int* in_sizes, int n_in,
                              void* d_out, int out_size)
{
    const float* z    = (const float*)d_in[0];
    const float* mask = (const float*)d_in[1];
    const float* ln_w = (const float*)d_in[2];
    const float* ln_b = (const float*)d_in[3];
    const float* Wq   = (const float*)d_in[4];
    const float* Wk   = (const float*)d_in[5];
    const float* Wv   = (const float*)d_in[6];
    const float* Wb   = (const float*)d_in[7];
    const float* Wg   = (const float*)d_in[8];
    const float* bg   = (const float*)d_in[9];
    const float* Wo   = (const float*)d_in[10];
    const float* bo   = (const float*)d_in[11];
    float* out = (float*)d_out;

    const int MAIN_SMEM = 192512;
    const int OUT_SMEM  = 2*64*WS*2 + 128*WS*2;   // 69632
    cudaFuncSetAttribute(k_main, cudaFuncAttributeMaxDynamicSharedMemorySize, MAIN_SMEM);
    cudaFuncSetAttribute(k_out,  cudaFuncAttributeMaxDynamicSharedMemorySize, OUT_SMEM);

    k_ln  <<<5 + NP/64, 512>>>(z, ln_w, ln_b, Wb, mask, Wq, Wk, Wv, Wg, Wo);
    k_main<<<dim3(L,NH), 512, MAIN_SMEM>>>(bg);
    k_out <<<296, 256, OUT_SMEM>>>(bo, out);
}

// round 17
// speedup vs baseline: 1.0683x; 1.0683x over previous
#include <cuda_runtime.h>
#include <cuda_fp16.h>
#include <math.h>
#include <stdint.h>

#define L   256
#define DM  128
#define NH  4
#define DK  32
#define NP  (L*L)
#define WS  136   // big-tile stride (halves)
#define AS  40    // small-tile stride (halves)

__device__ __align__(16) __half g_att[NP*DM];
__device__ __align__(16) __half g_zn[NP*DM];     // LN output, half
__device__ __align__(16) __half g_biasH[NH*NP];  // [h][i*L+j], *log2e, mask-folded
__device__ __align__(16) __half g_wT[5*128*WS];  // half W images [k][n], padded

__device__ __forceinline__ uint32_t smem_u32(const void* p){
    uint32_t a;
    asm("{ .reg .u64 t; cvta.to.shared.u64 t, %1; cvt.u32.u64 %0, t; }" : "=r"(a) : "l"(p));
    return a;
}
__device__ __forceinline__ void mma16(float* c, const uint32_t* a, const uint32_t* b){
    asm volatile("mma.sync.aligned.m16n8k16.row.col.f32.f16.f16.f32 "
        "{%0,%1,%2,%3}, {%4,%5,%6,%7}, {%8,%9}, {%0,%1,%2,%3};\n"
        : "+f"(c[0]), "+f"(c[1]), "+f"(c[2]), "+f"(c[3])
        : "r"(a[0]), "r"(a[1]), "r"(a[2]), "r"(a[3]), "r"(b[0]), "r"(b[1]));
}
__device__ __forceinline__ void ldsm4(uint32_t* r, uint32_t a){
    asm volatile("ldmatrix.sync.aligned.m8n8.x4.shared.b16 {%0,%1,%2,%3}, [%4];"
        : "=r"(r[0]), "=r"(r[1]), "=r"(r[2]), "=r"(r[3]) : "r"(a));
}
__device__ __forceinline__ void ldsm4t(uint32_t* r, uint32_t a){
    asm volatile("ldmatrix.sync.aligned.m8n8.x4.trans.shared.b16 {%0,%1,%2,%3}, [%4];"
        : "=r"(r[0]), "=r"(r[1]), "=r"(r[2]), "=r"(r[3]) : "r"(a));
}
__device__ __forceinline__ void ldsm2t(uint32_t* r, uint32_t a){
    asm volatile("ldmatrix.sync.aligned.m8n8.x2.trans.shared.b16 {%0,%1}, [%2];"
        : "=r"(r[0]), "=r"(r[1]) : "r"(a));
}
__device__ __forceinline__ uint32_t h2u(__half2 h){ return *(uint32_t*)&h; }
__device__ __forceinline__ float ex2(float x){
    float r; asm("ex2.approx.f32 %0, %1;" : "=f"(r) : "f"(x)); return r;
}
__device__ __forceinline__ void cpa16(uint32_t sdst, const void* gsrc){
    asm volatile("cp.async.cg.shared.global [%0], [%1], 16;" :: "r"(sdst), "l"(gsrc));
}
#define CP_COMMIT() asm volatile("cp.async.commit_group;" ::: "memory")
#define CP_WAIT0()  asm volatile("cp.async.wait_group 0;" ::: "memory")

// ---------------------------------------------------------------------------
// K1: blocks 0..4: weight images; blocks 5+: LN + bias. 256 thr/block.
// ---------------------------------------------------------------------------
__global__ __launch_bounds__(256) void k_ln(const float* __restrict__ z,
    const float* __restrict__ ln_w, const float* __restrict__ ln_b,
    const float* __restrict__ Wb, const float* __restrict__ mask,
    const float* __restrict__ Wq, const float* __restrict__ Wk,
    const float* __restrict__ Wv, const float* __restrict__ Wg,
    const float* __restrict__ Wo)
{
    if (blockIdx.x < 5){
        int m = blockIdx.x;
        const float* W = (m==0)?Wq:(m==1)?Wk:(m==2)?Wv:(m==3)?Wg:Wo;
        __half* dst = g_wT + m*128*WS;
        for (int e = threadIdx.x; e < 128*32; e += 256){
            int k = e>>5, c4 = e&31;
            float4 v = *(const float4*)&W[k*128 + c4*4];
            uint2 u = { h2u(__floats2half2_rn(v.x, v.y)), h2u(__floats2half2_rn(v.z, v.w)) };
            *(uint2*)&dst[k*WS + c4*4] = u;
        }
        return;
    }
    const float LOG2E = 1.4426950408889634f;
    int w = threadIdx.x>>5, lane = threadIdx.x&31;
    int pbase = (blockIdx.x-5)*32 + w*4;
    float4 lw = *(const float4*)&ln_w[lane*4];
    float4 lb = *(const float4*)&ln_b[lane*4];
    float4 w0 = *(const float4*)&Wb[(4*lane+0)*NH];
    float4 w1 = *(const float4*)&Wb[(4*lane+1)*NH];
    float4 w2 = *(const float4*)&Wb[(4*lane+2)*NH];
    float4 w3 = *(const float4*)&Wb[(4*lane+3)*NH];
    #pragma unroll
    for (int pp=0; pp<4; pp++){
        int p = pbase + pp;
        float4 x = *(const float4*)&z[(size_t)p*DM + lane*4];
        float s = x.x+x.y+x.z+x.w;
        float sq = x.x*x.x+x.y*x.y+x.z*x.z+x.w*x.w;
        #pragma unroll
        for (int o=16;o>0;o>>=1){
            s  += __shfl_xor_sync(0xffffffffu, s,  o);
            sq += __shfl_xor_sync(0xffffffffu, sq, o);
        }
        float mu = s*(1.0f/DM);
        float var = fmaxf(sq*(1.0f/DM) - mu*mu, 0.0f);
        float rstd = rsqrtf(var + 1e-5f);
        float zn0=(x.x-mu)*rstd*lw.x+lb.x, zn1=(x.y-mu)*rstd*lw.y+lb.y;
        float zn2=(x.z-mu)*rstd*lw.z+lb.z, zn3=(x.w-mu)*rstd*lw.w+lb.w;
        uint2 u = { h2u(__floats2half2_rn(zn0,zn1)), h2u(__floats2half2_rn(zn2,zn3)) };
        *(uint2*)&g_zn[(size_t)p*DM + lane*4] = u;
        float a0 = zn0*w0.x+zn1*w1.x+zn2*w2.x+zn3*w3.x;
        float a1 = zn0*w0.y+zn1*w1.y+zn2*w2.y+zn3*w3.y;
        float a2 = zn0*w0.z+zn1*w1.z+zn2*w2.z+zn3*w3.z;
        float a3 = zn0*w0.w+zn1*w1.w+zn2*w2.w+zn3*w3.w;
        #pragma unroll
        for (int o=16;o>0;o>>=1){
            a0 += __shfl_xor_sync(0xffffffffu, a0, o);
            a1 += __shfl_xor_sync(0xffffffffu, a1, o);
            a2 += __shfl_xor_sync(0xffffffffu, a2, o);
            a3 += __shfl_xor_sync(0xffffffffu, a3, o);
        }
        if (lane==0){
            float mf = mask[p>>8]*mask[p&255];
            float ninf = -__int_as_float(0x7f800000);
            g_biasH[0*NP+p] = __float2half(mf>0.f ? a0*LOG2E : ninf);
            g_biasH[1*NP+p] = __float2half(mf>0.f ? a1*LOG2E : ninf);
            g_biasH[2*NP+p] = __float2half(mf>0.f ? a2*LOG2E : ninf);
            g_biasH[3*NP+p] = __float2half(mf>0.f ? a3*LOG2E : ninf);
        }
    }
}

// ---------------------------------------------------------------------------
// K2: fused per (row r, head h): proj -> attention -> g_att. grid (L, NH).
// Staging via cp.async (R14 body otherwise).
// ---------------------------------------------------------------------------
__global__ __launch_bounds__(512,1) void k_main(const float* __restrict__ bg)
{
    extern __shared__ char smem[];
    __half* As = (__half*)smem;
    __half* Qt = (__half*)(smem + 69632);
    __half* Kt = Qt + 256*AS;
    __half* Vt = Kt + 256*AS;
    __half* Gt = Vt + 256*AS;
    __half* Wsl = Gt + 256*AS;
    uint32_t sAs = smem_u32(As), sQ = smem_u32(Qt), sK = smem_u32(Kt),
             sV = smem_u32(Vt), sWsl = smem_u32(Wsl);
    int r = blockIdx.x, h = blockIdx.y;
    int tid = threadIdx.x, w = tid>>5, lane = tid&31, g = lane>>2, t4 = lane&3;
    const float SC = 0.17677669529663687f * 1.4426950408889634f;

    // stage As (64KB) + Wsl (40KB) via cp.async; ones column via STS
    for (int e = tid; e < 4096; e += 512){
        int row = e>>4, c = e&15;
        cpa16(sAs + (row*WS + c*8)*2, &g_zn[(size_t)(r*L+row)*DM + c*8]);
    }
    for (int e = tid; e < 2048; e += 512){
        int m = e>>9, k = (e>>2)&127, c = e&3;
        cpa16(sWsl + (m*128*AS + k*AS + c*8)*2,
              &g_wT[m*128*WS + k*WS + h*32 + c*8]);
    }
    if (tid < 256){
        uint4 ones = { 0x00003C00u, 0u, 0u, 0u };
        *(uint4*)&Vt[tid*AS + 32] = ones;
    }
    CP_COMMIT();
    CP_WAIT0();
    __syncthreads();
    {
        int wm = w>>1, wn = w&1, rb = wm*32;
        uint32_t afrag[8][2][4];
        #pragma unroll
        for (int kc=0; kc<8; kc++)
            #pragma unroll
            for (int mt=0; mt<2; mt++)
                ldsm4(afrag[kc][mt],
                      sAs + ((rb + mt*16 + (lane&15))*WS + kc*16 + ((lane>>4)<<3))*2);
        #pragma unroll 1
        for (int mode=0; mode<4; mode++){
            uint32_t sWm = sWsl + mode*(128*AS*2);
            __half* Tt = (mode==0)?Qt:(mode==1)?Kt:(mode==2)?Vt:Gt;
            float acc[2][2][4];
            #pragma unroll
            for (int mt=0;mt<2;mt++)
                #pragma unroll
                for (int nt=0;nt<2;nt++)
                    #pragma unroll
                    for (int u=0;u<4;u++) acc[mt][nt][u]=0.f;
            #pragma unroll
            for (int kc=0; kc<8; kc++){
                int k0 = kc*16;
                uint32_t b[4];
                ldsm4t(b, sWm + ((k0 + (lane&7) + (((lane>>3)&1)<<3))*AS
                                  + wn*16 + ((lane>>4)<<3))*2);
                #pragma unroll
                for (int mt=0;mt<2;mt++){
                    mma16(acc[mt][0], afrag[kc][mt], &b[0]);
                    mma16(acc[mt][1], afrag[kc][mt], &b[2]);
                }
            }
            #pragma unroll
            for (int mt=0;mt<2;mt++)
                #pragma unroll
                for (int nt=0;nt<2;nt++){
                    int col = wn*16 + nt*8 + 2*t4;
                    #pragma unroll
                    for (int rp=0;rp<2;rp++){
                        int row = rb + mt*16 + g + 8*rp;
                        float v0 = acc[mt][nt][2*rp], v1 = acc[mt][nt][2*rp+1];
                        if (mode==0){ v0 *= SC; v1 *= SC; }
                        else if (mode==3){
                            v0 = 1.f/(1.f + __expf(-(v0 + bg[h*32+col])));
                            v1 = 1.f/(1.f + __expf(-(v1 + bg[h*32+col+1])));
                        }
                        *(__half2*)&Tt[row*AS + col] = __floats2half2_rn(v0, v1);
                    }
                }
        }
    }
    __syncthreads();
    {
        int rb = w*16;
        uint32_t qa[2][4];
        #pragma unroll
        for (int kc=0;kc<2;kc++)
            ldsm4(qa[kc], sQ + ((rb + (lane&15))*AS + kc*16 + ((lane>>4)<<3))*2);
        float oacc[4][4];
        float oaccS[4];
        #pragma unroll
        for (int nt=0;nt<4;nt++)
            #pragma unroll
            for (int u=0;u<4;u++) oacc[nt][u]=0.f;
        #pragma unroll
        for (int u=0;u<4;u++) oaccS[u]=0.f;

        #pragma unroll 1
        for (int jt=0; jt<4; jt++){
            int jb = jt*64;
            uint32_t breg[8][2];
            #pragma unroll
            for (int nt=0;nt<8;nt++){
                int j0 = jb + nt*8 + 2*t4;
                breg[nt][0] = *(const uint32_t*)&g_biasH[h*NP + (rb+g  )*L + j0];
                breg[nt][1] = *(const uint32_t*)&g_biasH[h*NP + (rb+g+8)*L + j0];
            }
            float sacc[8][4];
            #pragma unroll
            for (int nt=0;nt<8;nt++)
                #pragma unroll
                for (int u=0;u<4;u++) sacc[nt][u]=0.f;
            #pragma unroll
            for (int kc=0;kc<2;kc++){
                #pragma unroll
                for (int pr=0;pr<4;pr++){
                    uint32_t b[4];
                    ldsm4(b, sK + ((jb + pr*16 + (lane&7) + ((lane>>4)<<3))*AS
                                    + kc*16 + (((lane>>3)&1)<<3))*2);
                    mma16(sacc[2*pr],   qa[kc], &b[0]);
                    mma16(sacc[2*pr+1], qa[kc], &b[2]);
                }
            }
            uint32_t ph[8][2];
            #pragma unroll
            for (int nt=0;nt<8;nt++){
                #pragma unroll
                for (int rp=0;rp<2;rp++){
                    float2 bi = __half22float2(*(const __half2*)&breg[nt][rp]);
                    float p0 = ex2(sacc[nt][2*rp]   + bi.x);
                    float p1 = ex2(sacc[nt][2*rp+1] + bi.y);
                    ph[nt][rp] = h2u(__floats2half2_rn(p0, p1));
                }
            }
            #pragma unroll
            for (int kc2=0;kc2<4;kc2++){
                uint32_t pa[4] = { ph[2*kc2][0], ph[2*kc2][1], ph[2*kc2+1][0], ph[2*kc2+1][1] };
                #pragma unroll
                for (int pr=0;pr<2;pr++){
                    uint32_t b[4];
                    ldsm4t(b, sV + ((jb + kc2*16 + (lane&7) + (((lane>>3)&1)<<3))*AS
                                     + pr*16 + ((lane>>4)<<3))*2);
                    mma16(oacc[2*pr],   pa, &b[0]);
                    mma16(oacc[2*pr+1], pa, &b[2]);
                }
                uint32_t bS[2];
                ldsm2t(bS, sV + ((jb + kc2*16 + (lane&7) + (((lane>>3)&1)<<3))*AS + 32)*2);
                mma16(oaccS, pa, bS);
            }
        }
        float s0 = __shfl_sync(0xffffffffu, oaccS[0], lane & ~3);
        float s1 = __shfl_sync(0xffffffffu, oaccS[2], lane & ~3);
        float rinv[2] = { 1.f/s0, 1.f/s1 };
        #pragma unroll
        for (int nt=0;nt<4;nt++)
            #pragma unroll
            for (int rp=0;rp<2;rp++){
                int i = rb + g + 8*rp;
                int d = nt*8 + 2*t4;
                float2 gf = __half22float2(*(__half2*)&Gt[i*AS + d]);
                *(__half2*)&g_att[(size_t)(r*L+i)*DM + h*DK + d] = __floats2half2_rn(
                    oacc[nt][2*rp]  *rinv[rp]*gf.x,
                    oacc[nt][2*rp+1]*rinv[rp]*gf.y);
            }
    }
}

// ---------------------------------------------------------------------------
// K3: out = g_att @ Wo + bo. PERSISTENT: 296 CTAs x 256 thr, 2 CTAs/SM.
// ---------------------------------------------------------------------------
__global__ __launch_bounds__(256,2) void k_out(const float* __restrict__ bo,
                                               float* __restrict__ dout)
{
    extern __shared__ char smem[];
    __half* At0 = (__half*)smem;
    __half* At1 = (__half*)(smem + 64*WS*2);
    __half* Ws  = (__half*)(smem + 2*64*WS*2);
    uint32_t sAtB[2] = { smem_u32(At0), smem_u32(At1) };
    uint32_t sW = smem_u32(Ws);
    int tid = threadIdx.x, w = tid>>5, lane = tid&31, g = lane>>2, t4 = lane&3;
    int wm = w>>2, wn = w&3;

    for (int e = tid; e < 128*WS/8; e += 256)
        ((uint4*)Ws)[e] = ((const uint4*)(g_wT + 4*128*WS))[e];
    {
        int p0 = blockIdx.x*64;
        for (int e = tid; e < 1024; e += 256){
            int row = e>>4, c = e&15;
            ((uint4*)At0)[row*17 + c] = ((const uint4*)g_att)[(size_t)(p0+row)*16 + c];
        }
    }
    __syncthreads();

    float boL[4][2];
    #pragma unroll
    for (int nt=0;nt<4;nt++){
        boL[nt][0] = bo[wn*32 + nt*8 + 2*t4];
        boL[nt][1] = bo[wn*32 + nt*8 + 2*t4 + 1];
    }

    int buf = 0;
    for (int pb = blockIdx.x; pb < 1024; pb += gridDim.x){
        int nxt = pb + gridDim.x;
        if (nxt < 1024){
            __half* Atn = buf ? At0 : At1;
            int p0n = nxt*64;
            for (int e = tid; e < 1024; e += 256){
                int row = e>>4, c = e&15;
                ((uint4*)Atn)[row*17 + c] = ((const uint4*)g_att)[(size_t)(p0n+row)*16 + c];
            }
        }
        uint32_t sAt = sAtB[buf];
        int p0 = pb*64;
        int rb = wm*32;
        float acc[2][4][4];
        #pragma unroll
        for (int mt=0;mt<2;mt++)
            #pragma unroll
            for (int nt=0;nt<4;nt++)
                #pragma unroll
                for (int u=0;u<4;u++) acc[mt][nt][u]=0.f;
        #pragma unroll
        for (int kc=0; kc<8; kc++){
            int k0 = kc*16;
            uint32_t a[2][4];
            #pragma unroll
            for (int mt=0;mt<2;mt++)
                ldsm4(a[mt], sAt + ((rb + mt*16 + (lane&15))*WS + k0 + ((lane>>4)<<3))*2);
            uint32_t b[4][4];
            #pragma unroll
            for (int pr=0;pr<2;pr++)
                ldsm4t(b[2*pr], sW + ((k0 + (lane&7) + (((lane>>3)&1)<<3))*WS
                                       + wn*32 + pr*16 + ((lane>>4)<<3))*2);
            #pragma unroll
            for (int mt=0;mt<2;mt++)
                #pragma unroll
                for (int nt=0;nt<4;nt++)
                    mma16(acc[mt][nt], a[mt], &b[nt&~1][(nt&1)*2]);
        }
        #pragma unroll
        for (int mt=0;mt<2;mt++)
            #pragma unroll
            for (int nt=0;nt<4;nt++){
                int col = wn*32 + nt*8 + 2*t4;
                #pragma unroll
                for (int rp=0;rp<2;rp++){
                    int row = p0 + rb + mt*16 + g + 8*rp;
                    float2 o2 = { acc[mt][nt][2*rp] + boL[nt][0],
                                  acc[mt][nt][2*rp+1] + boL[nt][1] };
                    *(float2*)&dout[(size_t)row*DM + col] = o2;
                }
            }
        buf ^= 1;
        __syncthreads();
    }
}

// ---------------------------------------------------------------------------
extern "C" void kernel_launch(void* const* d_in, const int* in_sizes, int n_in,
                              void* d_out, int out_size)
{
    const float* z    = (const float*)d_in[0];
    const float* mask = (const float*)d_in[1];
    const float* ln_w = (const float*)d_in[2];
    const float* ln_b = (const float*)d_in[3];
    const float* Wq   = (const float*)d_in[4];
    const float* Wk   = (const float*)d_in[5];
    const float* Wv   = (const float*)d_in[6];
    const float* Wb   = (const float*)d_in[7];
    const float* Wg   = (const float*)d_in[8];
    const float* bg   = (const float*)d_in[9];
    const float* Wo   = (const float*)d_in[10];
    const float* bo   = (const float*)d_in[11];
    float* out = (float*)d_out;

    const int MAIN_SMEM = 192512;
    const int OUT_SMEM  = 2*64*WS*2 + 128*WS*2;   // 69632
    cudaFuncSetAttribute(k_main, cudaFuncAttributeMaxDynamicSharedMemorySize, MAIN_SMEM);
    cudaFuncSetAttribute(k_out,  cudaFuncAttributeMaxDynamicSharedMemorySize, OUT_SMEM);

    k_ln  <<<5 + NP/32, 256>>>(z, ln_w, ln_b, Wb, mask, Wq, Wk, Wv, Wg, Wo);
    k_main<<<dim3(L,NH), 512, MAIN_SMEM>>>(bg);
    k_out <<<296, 256, OUT_SMEM>>>(bo, out);
}